// round 5
// baseline (speedup 1.0000x reference)
#include <cuda_runtime.h>
#include <cstdint>
#include <cstddef>

#define NPTS   4096
#define MANCH  128
#define GC0    64
#define GC1    128
#define KNN    32
#define RR2    0.0225f
#define GTOT   64
#define FPS_THREADS 512
#define CONV_THREADS 256

// Weights live in the constant bank: warp-uniform reads go through the
// LDCU uniform port (floor 1/cyc) instead of the saturated LSU/smem pipe.
__constant__ float cWm[GC1 * GC0];
__constant__ float cWd[GC0 * 4];

// Exact (non-FMA-contracted) squared distance, matching the reference's
// evaluation so discrete decisions (argmax / radius threshold) agree exactly.
__device__ __forceinline__ float dist2_precise(float ax, float ay, float az,
                                               float bx, float by, float bz) {
    float dx = __fsub_rn(ax, bx);
    float dy = __fsub_rn(ay, by);
    float dz = __fsub_rn(az, bz);
    return __fadd_rn(__fadd_rn(__fmul_rn(dx, dx), __fmul_rn(dy, dy)),
                     __fmul_rn(dz, dz));
}

// ---- packed f32x2 helpers ----
__device__ __forceinline__ unsigned long long pk2(float lo, float hi) {
    unsigned long long r;
    asm("mov.b64 %0, {%1, %2};" : "=l"(r) : "f"(lo), "f"(hi));
    return r;
}
__device__ __forceinline__ void upk2(float& lo, float& hi, unsigned long long v) {
    asm("mov.b64 {%0, %1}, %2;" : "=f"(lo), "=f"(hi) : "l"(v));
}
__device__ __forceinline__ unsigned long long ffma2(unsigned long long a,
                                                    unsigned long long b,
                                                    unsigned long long c) {
    unsigned long long d;
    asm("fma.rn.f32x2 %0, %1, %2, %3;" : "=l"(d) : "l"(a), "l"(b), "l"(c));
    return d;
}
__device__ __forceinline__ unsigned long long fadd2(unsigned long long a,
                                                    unsigned long long b) {
    unsigned long long d;
    asm("add.rn.f32x2 %0, %1, %2;" : "=l"(d) : "l"(a), "l"(b));
    return d;
}
// warp max of a non-negative float via integer redux (bit-monotonic for >=0)
__device__ __forceinline__ float warp_max_nonneg(float v) {
    unsigned u = __float_as_uint(v), r;
    asm("redux.sync.max.u32 %0, %1, 0xffffffff;" : "=r"(r) : "r"(u));
    return __uint_as_float(r);
}

// ---------------------------------------------------------------------------
// Kernel A: furthest point sampling. One block per group (64 blocks).
// ---------------------------------------------------------------------------
__global__ void __launch_bounds__(FPS_THREADS) fps_kernel(
    const float* __restrict__ xyzs, float* __restrict__ out) {
    extern __shared__ float sm[];
    float* sx = sm;
    float* sy = sm + NPTS;
    float* sz = sm + 2 * NPTS;
    __shared__ float redV[16];
    __shared__ int   redI[16];
    __shared__ float curP[3];

    int g = blockIdx.x;
    int b = g >> 4, f = g & 15;
    int t = 2 * f;
    const float* frame = xyzs + ((size_t)(b * 32 + t)) * NPTS * 3;
    int tid = threadIdx.x;

    for (int i = tid; i < NPTS; i += FPS_THREADS) {
        sx[i] = frame[3 * i + 0];
        sy[i] = frame[3 * i + 1];
        sz[i] = frame[3 * i + 2];
    }
    __syncthreads();

    float prx[8], pry[8], prz[8], dist[8];
#pragma unroll
    for (int s = 0; s < 8; s++) {
        int i = tid + s * FPS_THREADS;
        prx[s] = sx[i]; pry[s] = sy[i]; prz[s] = sz[i];
        dist[s] = 1e10f;
    }

    if (tid == 0) {
        float* ap = out + (size_t)g * MANCH * 3;
        ap[0] = sx[0]; ap[1] = sy[0]; ap[2] = sz[0];
    }

    float px = sx[0], py = sy[0], pz = sz[0];

    for (int step = 1; step < MANCH; step++) {
        float bv = -1.0f;
        int   bi = NPTS;
#pragma unroll
        for (int s = 0; s < 8; s++) {
            int i = tid + s * FPS_THREADS;
            float d2 = dist2_precise(prx[s], pry[s], prz[s], px, py, pz);
            float dd = fminf(dist[s], d2);
            dist[s] = dd;
            if (dd > bv || (dd == bv && i < bi)) { bv = dd; bi = i; }
        }
#pragma unroll
        for (int off = 16; off; off >>= 1) {
            float ov = __shfl_down_sync(0xffffffffu, bv, off);
            int   oi = __shfl_down_sync(0xffffffffu, bi, off);
            if (ov > bv || (ov == bv && oi < bi)) { bv = ov; bi = oi; }
        }
        if ((tid & 31) == 0) { redV[tid >> 5] = bv; redI[tid >> 5] = bi; }
        __syncthreads();
        if (tid < 32) {
            bv = (tid < 16) ? redV[tid] : -1.0f;
            bi = (tid < 16) ? redI[tid] : NPTS;
#pragma unroll
            for (int off = 8; off; off >>= 1) {
                float ov = __shfl_down_sync(0xffffffffu, bv, off);
                int   oi = __shfl_down_sync(0xffffffffu, bi, off);
                if (ov > bv || (ov == bv && oi < bi)) { bv = ov; bi = oi; }
            }
            if (tid == 0) {
                curP[0] = sx[bi]; curP[1] = sy[bi]; curP[2] = sz[bi];
                float* ap = out + ((size_t)g * MANCH + step) * 3;
                ap[0] = sx[bi]; ap[1] = sy[bi]; ap[2] = sz[bi];
            }
        }
        __syncthreads();
        px = curP[0]; py = curP[1]; pz = curP[2];
    }
}

// ---------------------------------------------------------------------------
// Kernel B: ball query + 2-layer MLP + max-over-k + sum-over-dt.
// Grid (8,64), block 256 = 8 warps; warp owns 2 anchors sequentially.
// Weights come from __constant__ (uniform port); smem holds points only.
// ---------------------------------------------------------------------------
__global__ void __launch_bounds__(CONV_THREADS, 2) conv_kernel(
    const float* __restrict__ xyzs,
    float* __restrict__ out) {
    extern __shared__ float sm[];
    float* sx  = sm;
    float* sy  = sm + NPTS;
    float* sz  = sm + 2 * NPTS;
    int*   sidx = (int*)(sm + 3 * NPTS);  // 8 warps * 32

    int tile = blockIdx.x, g = blockIdx.y;
    int b = g >> 4, f = g & 15;
    int tid = threadIdx.x, warp = tid >> 5, lane = tid & 31;

    int m0 = tile * 16 + warp * 2;
    const float* ap0 = out + ((size_t)g * MANCH + m0) * 3;
    float anc[2][3];
    anc[0][0] = ap0[0]; anc[0][1] = ap0[1]; anc[0][2] = ap0[2];
    anc[1][0] = ap0[3]; anc[1][1] = ap0[4]; anc[1][2] = ap0[5];

    float acc[2][4];
#pragma unroll
    for (int a = 0; a < 2; a++)
#pragma unroll
        for (int j = 0; j < 4; j++) acc[a][j] = 0.0f;

    int* ib = sidx + warp * KNN;

    for (int dt = -1; dt <= 1; dt++) {
        int t = 2 * f + dt;
        t = t < 0 ? 0 : (t > 31 ? 31 : t);
        const float* frame = xyzs + ((size_t)(b * 32 + t)) * NPTS * 3;
        __syncthreads();  // previous dt's smem reads complete before overwrite
        for (int i = tid; i < NPTS; i += CONV_THREADS) {
            sx[i] = frame[3 * i + 0];
            sy[i] = frame[3 * i + 1];
            sz[i] = frame[3 * i + 2];
        }
        __syncthreads();
        float dtf = (float)dt;

        for (int a = 0; a < 2; a++) {
            float ax = anc[a][0], ay = anc[a][1], az = anc[a][2];

            // ---- ball query: first KNN indices with d2 < R^2, ascending
            int count = 0;
            for (int base = 0; base < NPTS && count < KNN; base += 32) {
                int i = base + lane;
                float d2 = dist2_precise(ax, ay, az, sx[i], sy[i], sz[i]);
                bool within = d2 < RR2;
                unsigned msk = __ballot_sync(0xffffffffu, within);
                int pos = count + __popc(msk & ((1u << lane) - 1u));
                if (within && pos < KNN) ib[pos] = i;
                count += __popc(msk);
            }
            __syncwarp();
            int myIdx = 0;  // no valid neighbor -> index 0 (reference semantics)
            if (count > 0) myIdx = ib[lane < count ? lane : 0];

            float dx = sx[myIdx] - ax;
            float dy = sy[myIdx] - ay;
            float dz = sz[myIdx] - az;

            // ---- layer 1: h1 = relu(Wd @ [dx,dy,dz,dt]), packed over i-pairs
            unsigned long long h1[GC0 / 2];
#pragma unroll
            for (int q = 0; q < GC0 / 2; q++) {
                float4 w0 = ((const float4*)cWd)[2 * q];
                float4 w1 = ((const float4*)cWd)[2 * q + 1];
                float v0 = fmaf(w0.x, dx, fmaf(w0.y, dy, fmaf(w0.z, dz, w0.w * dtf)));
                float v1 = fmaf(w1.x, dx, fmaf(w1.y, dy, fmaf(w1.z, dz, w1.w * dtf)));
                h1[q] = pk2(fmaxf(v0, 0.0f), fmaxf(v1, 0.0f));
            }

            // ---- layer 2 (Wm via uniform-const port) + max over k + sum dt
#pragma unroll 2
            for (int o = 0; o < GC1; o++) {
                const ulonglong2* wr = (const ulonglong2*)(cWm + o * GC0);
                unsigned long long s0 = 0ull, s1 = 0ull, s2 = 0ull, s3 = 0ull;
#pragma unroll
                for (int q = 0; q < 16; q += 2) {
                    ulonglong2 wA = wr[q];
                    ulonglong2 wB = wr[q + 1];
                    s0 = ffma2(h1[2 * q + 0], wA.x, s0);
                    s1 = ffma2(h1[2 * q + 1], wA.y, s1);
                    s2 = ffma2(h1[2 * q + 2], wB.x, s2);
                    s3 = ffma2(h1[2 * q + 3], wB.y, s3);
                }
                unsigned long long tt = fadd2(fadd2(s0, s2), fadd2(s1, s3));
                float lo, hi;
                upk2(lo, hi, tt);
                float s = fmaxf(lo + hi, 0.0f);
                s = warp_max_nonneg(s);
                if (lane == (o & 31)) acc[a][o >> 5] += s;
            }
        }
    }

    // ---- write new_features: out[b,f,o,m] after the new_xyzs block
    float* feat = out + (size_t)GTOT * MANCH * 3;
#pragma unroll
    for (int a = 0; a < 2; a++) {
        int m = m0 + a;
#pragma unroll
        for (int j = 0; j < 4; j++) {
            int o = j * 32 + lane;
            feat[((size_t)g * GC1 + o) * MANCH + m] = acc[a][j];
        }
    }
}

extern "C" void kernel_launch(void* const* d_in, const int* in_sizes, int n_in,
                              void* d_out, int out_size) {
    const float* xyzs = (const float*)d_in[0];
    const float* Wd   = (const float*)d_in[1];
    const float* Wm   = (const float*)d_in[2];
    float* out = (float*)d_out;

    // Stage weights into the constant bank (async D2D copies; graph-capturable)
    cudaMemcpyToSymbolAsync(cWd, Wd, GC0 * 4 * sizeof(float), 0,
                            cudaMemcpyDeviceToDevice);
    cudaMemcpyToSymbolAsync(cWm, Wm, GC1 * GC0 * sizeof(float), 0,
                            cudaMemcpyDeviceToDevice);

    size_t smA = (size_t)3 * NPTS * sizeof(float);
    size_t smB = (size_t)3 * NPTS * sizeof(float) + 8 * KNN * sizeof(int);

    cudaFuncSetAttribute(fps_kernel,  cudaFuncAttributeMaxDynamicSharedMemorySize, (int)smA);
    cudaFuncSetAttribute(conv_kernel, cudaFuncAttributeMaxDynamicSharedMemorySize, (int)smB);

    fps_kernel<<<GTOT, FPS_THREADS, smA>>>(xyzs, out);
    conv_kernel<<<dim3(8, GTOT), CONV_THREADS, smB>>>(xyzs, out);
}

// round 6
// speedup vs baseline: 1.4997x; 1.4997x over previous
#include <cuda_runtime.h>
#include <cstdint>
#include <cstddef>

#define NPTS   4096
#define MANCH  128
#define GC0    64
#define GC1    128
#define KNN    32
#define RR2    0.0225f
#define GTOT   64
#define FPS_THREADS 1024
#define CONV_THREADS 256
#define QSPLIT 11   // q < QSPLIT from smem (LDS), rest from const (LDC)

// Secondary copy of Wm in the constant bank: offloads 5/16 of the weight
// stream per o-iteration onto the (half-rate) constant port so the LSU/smem
// pipe drops below the FMA floor.
__constant__ __align__(16) float cWm[GC1 * GC0];

// Exact (non-FMA-contracted) squared distance, matching the reference's
// evaluation so discrete decisions (argmax / radius threshold) agree exactly.
__device__ __forceinline__ float dist2_precise(float ax, float ay, float az,
                                               float bx, float by, float bz) {
    float dx = __fsub_rn(ax, bx);
    float dy = __fsub_rn(ay, by);
    float dz = __fsub_rn(az, bz);
    return __fadd_rn(__fadd_rn(__fmul_rn(dx, dx), __fmul_rn(dy, dy)),
                     __fmul_rn(dz, dz));
}

// ---- packed f32x2 helpers ----
__device__ __forceinline__ unsigned long long pk2(float lo, float hi) {
    unsigned long long r;
    asm("mov.b64 %0, {%1, %2};" : "=l"(r) : "f"(lo), "f"(hi));
    return r;
}
__device__ __forceinline__ void upk2(float& lo, float& hi, unsigned long long v) {
    asm("mov.b64 {%0, %1}, %2;" : "=f"(lo), "=f"(hi) : "l"(v));
}
__device__ __forceinline__ unsigned long long ffma2(unsigned long long a,
                                                    unsigned long long b,
                                                    unsigned long long c) {
    unsigned long long d;
    asm("fma.rn.f32x2 %0, %1, %2, %3;" : "=l"(d) : "l"(a), "l"(b), "l"(c));
    return d;
}
__device__ __forceinline__ unsigned long long fadd2(unsigned long long a,
                                                    unsigned long long b) {
    unsigned long long d;
    asm("add.rn.f32x2 %0, %1, %2;" : "=l"(d) : "l"(a), "l"(b));
    return d;
}
// warp max of a non-negative float via integer redux (bit-monotonic for >=0)
__device__ __forceinline__ float warp_max_nonneg(float v) {
    unsigned u = __float_as_uint(v), r;
    asm("redux.sync.max.u32 %0, %1, 0xffffffff;" : "=r"(r) : "r"(u));
    return __uint_as_float(r);
}

// ---------------------------------------------------------------------------
// Kernel A: furthest point sampling. One block per group (64 blocks),
// 1024 threads, 4 points/lane to shorten the serial per-step chain.
// ---------------------------------------------------------------------------
__global__ void __launch_bounds__(FPS_THREADS) fps_kernel(
    const float* __restrict__ xyzs, float* __restrict__ out) {
    extern __shared__ float sm[];
    float* sx = sm;
    float* sy = sm + NPTS;
    float* sz = sm + 2 * NPTS;
    __shared__ float redV[32];
    __shared__ int   redI[32];
    __shared__ float curP[3];

    int g = blockIdx.x;
    int b = g >> 4, f = g & 15;
    int t = 2 * f;
    const float* frame = xyzs + ((size_t)(b * 32 + t)) * NPTS * 3;
    int tid = threadIdx.x;

    for (int i = tid; i < NPTS; i += FPS_THREADS) {
        sx[i] = frame[3 * i + 0];
        sy[i] = frame[3 * i + 1];
        sz[i] = frame[3 * i + 2];
    }
    __syncthreads();

    float prx[4], pry[4], prz[4], dist[4];
#pragma unroll
    for (int s = 0; s < 4; s++) {
        int i = tid + s * FPS_THREADS;
        prx[s] = sx[i]; pry[s] = sy[i]; prz[s] = sz[i];
        dist[s] = 1e10f;
    }

    if (tid == 0) {
        float* ap = out + (size_t)g * MANCH * 3;
        ap[0] = sx[0]; ap[1] = sy[0]; ap[2] = sz[0];
    }

    float px = sx[0], py = sy[0], pz = sz[0];

    for (int step = 1; step < MANCH; step++) {
        float bv = -1.0f;
        int   bi = NPTS;
#pragma unroll
        for (int s = 0; s < 4; s++) {
            int i = tid + s * FPS_THREADS;
            float d2 = dist2_precise(prx[s], pry[s], prz[s], px, py, pz);
            float dd = fminf(dist[s], d2);
            dist[s] = dd;
            if (dd > bv || (dd == bv && i < bi)) { bv = dd; bi = i; }
        }
#pragma unroll
        for (int off = 16; off; off >>= 1) {
            float ov = __shfl_down_sync(0xffffffffu, bv, off);
            int   oi = __shfl_down_sync(0xffffffffu, bi, off);
            if (ov > bv || (ov == bv && oi < bi)) { bv = ov; bi = oi; }
        }
        if ((tid & 31) == 0) { redV[tid >> 5] = bv; redI[tid >> 5] = bi; }
        __syncthreads();
        if (tid < 32) {
            bv = redV[tid];
            bi = redI[tid];
#pragma unroll
            for (int off = 16; off; off >>= 1) {
                float ov = __shfl_down_sync(0xffffffffu, bv, off);
                int   oi = __shfl_down_sync(0xffffffffu, bi, off);
                if (ov > bv || (ov == bv && oi < bi)) { bv = ov; bi = oi; }
            }
            if (tid == 0) {
                curP[0] = sx[bi]; curP[1] = sy[bi]; curP[2] = sz[bi];
                float* ap = out + ((size_t)g * MANCH + step) * 3;
                ap[0] = sx[bi]; ap[1] = sy[bi]; ap[2] = sz[bi];
            }
        }
        __syncthreads();
        px = curP[0]; py = curP[1]; pz = curP[2];
    }
}

// ---------------------------------------------------------------------------
// Kernel B: ball query + 2-layer MLP + max-over-k + sum-over-dt.
// Grid (8,64), block 256 = 8 warps; warp owns 2 anchors sequentially.
// Layer-2 weights split 11/5 between smem (LDS) and const (LDC) so neither
// port exceeds the FFMA2 floor.
// ---------------------------------------------------------------------------
__global__ void __launch_bounds__(CONV_THREADS, 2) conv_kernel(
    const float* __restrict__ xyzs,
    const float* __restrict__ Wd_g,
    const float* __restrict__ Wm_g,
    float* __restrict__ out) {
    extern __shared__ float sm[];
    float* sx  = sm;
    float* sy  = sm + NPTS;
    float* sz  = sm + 2 * NPTS;
    float* sWm = sm + 3 * NPTS;           // 128*64, 16B aligned
    float* sWd = sWm + GC1 * GC0;
    int*   sidx = (int*)(sWd + GC0 * 4);  // 8 warps * 32

    int tile = blockIdx.x, g = blockIdx.y;
    int b = g >> 4, f = g & 15;
    int tid = threadIdx.x, warp = tid >> 5, lane = tid & 31;

    for (int i = tid; i < GC1 * GC0; i += CONV_THREADS) sWm[i] = Wm_g[i];
    if (tid < GC0 * 4) sWd[tid] = Wd_g[tid];

    int m0 = tile * 16 + warp * 2;
    const float* ap0 = out + ((size_t)g * MANCH + m0) * 3;
    float anc[2][3];
    anc[0][0] = ap0[0]; anc[0][1] = ap0[1]; anc[0][2] = ap0[2];
    anc[1][0] = ap0[3]; anc[1][1] = ap0[4]; anc[1][2] = ap0[5];

    float acc[2][4];
#pragma unroll
    for (int a = 0; a < 2; a++)
#pragma unroll
        for (int j = 0; j < 4; j++) acc[a][j] = 0.0f;

    int* ib = sidx + warp * KNN;

    for (int dt = -1; dt <= 1; dt++) {
        int t = 2 * f + dt;
        t = t < 0 ? 0 : (t > 31 ? 31 : t);
        const float* frame = xyzs + ((size_t)(b * 32 + t)) * NPTS * 3;
        __syncthreads();  // previous dt's smem reads complete before overwrite
        for (int i = tid; i < NPTS; i += CONV_THREADS) {
            sx[i] = frame[3 * i + 0];
            sy[i] = frame[3 * i + 1];
            sz[i] = frame[3 * i + 2];
        }
        __syncthreads();
        float dtf = (float)dt;

        for (int a = 0; a < 2; a++) {
            float ax = anc[a][0], ay = anc[a][1], az = anc[a][2];

            // ---- ball query: first KNN indices with d2 < R^2, ascending
            int count = 0;
            for (int base = 0; base < NPTS && count < KNN; base += 32) {
                int i = base + lane;
                float d2 = dist2_precise(ax, ay, az, sx[i], sy[i], sz[i]);
                bool within = d2 < RR2;
                unsigned msk = __ballot_sync(0xffffffffu, within);
                int pos = count + __popc(msk & ((1u << lane) - 1u));
                if (within && pos < KNN) ib[pos] = i;
                count += __popc(msk);
            }
            __syncwarp();
            int myIdx = 0;  // no valid neighbor -> index 0 (reference semantics)
            if (count > 0) myIdx = ib[lane < count ? lane : 0];

            float dx = sx[myIdx] - ax;
            float dy = sy[myIdx] - ay;
            float dz = sz[myIdx] - az;

            // ---- layer 1: h1 = relu(Wd @ [dx,dy,dz,dt]), packed over i-pairs
            unsigned long long h1[GC0 / 2];
#pragma unroll
            for (int q = 0; q < GC0 / 2; q++) {
                float4 w0 = ((const float4*)sWd)[2 * q];
                float4 w1 = ((const float4*)sWd)[2 * q + 1];
                float v0 = fmaf(w0.x, dx, fmaf(w0.y, dy, fmaf(w0.z, dz, w0.w * dtf)));
                float v1 = fmaf(w1.x, dx, fmaf(w1.y, dy, fmaf(w1.z, dz, w1.w * dtf)));
                h1[q] = pk2(fmaxf(v0, 0.0f), fmaxf(v1, 0.0f));
            }

            // ---- layer 2: Wm split 11 rows-of-16B from smem + 5 from const
#pragma unroll 2
            for (int o = 0; o < GC1; o++) {
                const ulonglong2* wr_s = (const ulonglong2*)(sWm + o * GC0);
                const ulonglong2* wr_c = (const ulonglong2*)(cWm + o * GC0);
                unsigned long long s0 = 0ull, s1 = 0ull, s2 = 0ull, s3 = 0ull;
#pragma unroll
                for (int q = 0; q < 8; q++) {
                    ulonglong2 w = (2 * q + 1 < QSPLIT) ? wr_s[2 * q]
                                                        : wr_c[2 * q];
                    ulonglong2 w2 = (2 * q + 2 < QSPLIT) ? wr_s[2 * q + 1]
                                                         : wr_c[2 * q + 1];
                    // note: element (2q) uses smem while 2q < QSPLIT
                    if (2 * q < QSPLIT) w = wr_s[2 * q]; else w = wr_c[2 * q];
                    s0 = ffma2(h1[4 * q + 0], w.x,  s0);
                    s1 = ffma2(h1[4 * q + 1], w.y,  s1);
                    s2 = ffma2(h1[4 * q + 2], w2.x, s2);
                    s3 = ffma2(h1[4 * q + 3], w2.y, s3);
                }
                unsigned long long tt = fadd2(fadd2(s0, s2), fadd2(s1, s3));
                float lo, hi;
                upk2(lo, hi, tt);
                float s = fmaxf(lo + hi, 0.0f);
                s = warp_max_nonneg(s);
                if (lane == (o & 31)) acc[a][o >> 5] += s;
            }
        }
    }

    // ---- write new_features: out[b,f,o,m] after the new_xyzs block
    float* feat = out + (size_t)GTOT * MANCH * 3;
#pragma unroll
    for (int a = 0; a < 2; a++) {
        int m = m0 + a;
#pragma unroll
        for (int j = 0; j < 4; j++) {
            int o = j * 32 + lane;
            feat[((size_t)g * GC1 + o) * MANCH + m] = acc[a][j];
        }
    }
}

extern "C" void kernel_launch(void* const* d_in, const int* in_sizes, int n_in,
                              void* d_out, int out_size) {
    const float* xyzs = (const float*)d_in[0];
    const float* Wd   = (const float*)d_in[1];
    const float* Wm   = (const float*)d_in[2];
    float* out = (float*)d_out;

    // Constant-bank copy of Wm for the LDC share of the split.
    cudaMemcpyToSymbolAsync(cWm, Wm, GC1 * GC0 * sizeof(float), 0,
                            cudaMemcpyDeviceToDevice);

    size_t smA = (size_t)3 * NPTS * sizeof(float);
    size_t smB = ((size_t)3 * NPTS + GC1 * GC0 + GC0 * 4) * sizeof(float)
               + 8 * KNN * sizeof(int);

    cudaFuncSetAttribute(fps_kernel,  cudaFuncAttributeMaxDynamicSharedMemorySize, (int)smA);
    cudaFuncSetAttribute(conv_kernel, cudaFuncAttributeMaxDynamicSharedMemorySize, (int)smB);

    fps_kernel<<<GTOT, FPS_THREADS, smA>>>(xyzs, out);
    conv_kernel<<<dim3(8, GTOT), CONV_THREADS, smB>>>(xyzs, Wd, Wm, out);
}

// round 7
// speedup vs baseline: 3.6131x; 2.4092x over previous
#include <cuda_runtime.h>
#include <cstdint>
#include <cstddef>

#define NPTS   4096
#define MANCH  128
#define GC0    64
#define GC1    128
#define KNN    32
#define RR2    0.0225f
#define GTOT   64
#define FPS_THREADS 1024
#define CONV_THREADS 256

// Layer-1 weights (1KB — fits const cache, warp-uniform reads)
__constant__ float4 cWd[GC0];
// Layer-2 weights as tf32, pre-swizzled into m16n8k8 A-fragment layout:
// [mt(8)][kt(8)][lane(32)][r(4)]  (8192 words = 32KB, L1-resident)
__device__ uint32_t gWmF[8 * 8 * 128];

// Exact (non-FMA-contracted) squared distance: discrete decisions
// (FPS argmax / radius threshold) match the JAX reference bit-for-bit.
__device__ __forceinline__ float dist2_precise(float ax, float ay, float az,
                                               float bx, float by, float bz) {
    float dx = __fsub_rn(ax, bx);
    float dy = __fsub_rn(ay, by);
    float dz = __fsub_rn(az, bz);
    return __fadd_rn(__fadd_rn(__fmul_rn(dx, dx), __fmul_rn(dy, dy)),
                     __fmul_rn(dz, dz));
}

__device__ __forceinline__ uint32_t f2tf32(float f) {
    uint32_t r;
    asm("cvt.rna.tf32.f32 %0, %1;" : "=r"(r) : "f"(f));
    return r;
}

__device__ __forceinline__ void mma_tf32(float& d0, float& d1, float& d2, float& d3,
                                         uint32_t a0, uint32_t a1, uint32_t a2, uint32_t a3,
                                         uint32_t b0, uint32_t b1) {
    asm volatile(
        "mma.sync.aligned.m16n8k8.row.col.f32.tf32.tf32.f32 "
        "{%0,%1,%2,%3}, {%4,%5,%6,%7}, {%8,%9}, {%0,%1,%2,%3};"
        : "+f"(d0), "+f"(d1), "+f"(d2), "+f"(d3)
        : "r"(a0), "r"(a1), "r"(a2), "r"(a3), "r"(b0), "r"(b1));
}

// ---------------------------------------------------------------------------
// Prep: Wm -> tf32 A-fragments (fragment-major). One element per thread.
// ---------------------------------------------------------------------------
__global__ void prep_kernel(const float* __restrict__ Wm) {
    int idx = blockIdx.x * blockDim.x + threadIdx.x;  // 0..8191
    int fid = idx >> 7, rem = idx & 127;
    int l = rem >> 2, r = rem & 3;
    int mt = fid >> 3, kt = fid & 7;
    int gid = l >> 2, tig = l & 3;
    int row = mt * 16 + gid + (r & 1) * 8;   // o index
    int col = kt * 8 + tig + (r >> 1) * 4;   // channel index
    gWmF[idx] = f2tf32(Wm[row * GC0 + col]);
}

// ---------------------------------------------------------------------------
// Kernel A: furthest point sampling (unchanged; exact fp32).
// ---------------------------------------------------------------------------
__global__ void __launch_bounds__(FPS_THREADS) fps_kernel(
    const float* __restrict__ xyzs, float* __restrict__ out) {
    extern __shared__ float sm[];
    float* sx = sm;
    float* sy = sm + NPTS;
    float* sz = sm + 2 * NPTS;
    __shared__ float redV[32];
    __shared__ int   redI[32];
    __shared__ float curP[3];

    int g = blockIdx.x;
    int b = g >> 4, f = g & 15;
    int t = 2 * f;
    const float* frame = xyzs + ((size_t)(b * 32 + t)) * NPTS * 3;
    int tid = threadIdx.x;

    for (int i = tid; i < NPTS; i += FPS_THREADS) {
        sx[i] = frame[3 * i + 0];
        sy[i] = frame[3 * i + 1];
        sz[i] = frame[3 * i + 2];
    }
    __syncthreads();

    float prx[4], pry[4], prz[4], dist[4];
#pragma unroll
    for (int s = 0; s < 4; s++) {
        int i = tid + s * FPS_THREADS;
        prx[s] = sx[i]; pry[s] = sy[i]; prz[s] = sz[i];
        dist[s] = 1e10f;
    }

    if (tid == 0) {
        float* ap = out + (size_t)g * MANCH * 3;
        ap[0] = sx[0]; ap[1] = sy[0]; ap[2] = sz[0];
    }

    float px = sx[0], py = sy[0], pz = sz[0];

    for (int step = 1; step < MANCH; step++) {
        float bv = -1.0f;
        int   bi = NPTS;
#pragma unroll
        for (int s = 0; s < 4; s++) {
            int i = tid + s * FPS_THREADS;
            float d2 = dist2_precise(prx[s], pry[s], prz[s], px, py, pz);
            float dd = fminf(dist[s], d2);
            dist[s] = dd;
            if (dd > bv || (dd == bv && i < bi)) { bv = dd; bi = i; }
        }
#pragma unroll
        for (int off = 16; off; off >>= 1) {
            float ov = __shfl_down_sync(0xffffffffu, bv, off);
            int   oi = __shfl_down_sync(0xffffffffu, bi, off);
            if (ov > bv || (ov == bv && oi < bi)) { bv = ov; bi = oi; }
        }
        if ((tid & 31) == 0) { redV[tid >> 5] = bv; redI[tid >> 5] = bi; }
        __syncthreads();
        if (tid < 32) {
            bv = redV[tid];
            bi = redI[tid];
#pragma unroll
            for (int off = 16; off; off >>= 1) {
                float ov = __shfl_down_sync(0xffffffffu, bv, off);
                int   oi = __shfl_down_sync(0xffffffffu, bi, off);
                if (ov > bv || (ov == bv && oi < bi)) { bv = ov; bi = oi; }
            }
            if (tid == 0) {
                curP[0] = sx[bi]; curP[1] = sy[bi]; curP[2] = sz[bi];
                float* ap = out + ((size_t)g * MANCH + step) * 3;
                ap[0] = sx[bi]; ap[1] = sy[bi]; ap[2] = sz[bi];
            }
        }
        __syncthreads();
        px = curP[0]; py = curP[1]; pz = curP[2];
    }
}

// ---------------------------------------------------------------------------
// Kernel B: ball query + layer1 (fp32) + layer2 on tensor cores (tf32 mma)
// + max-over-k in fragments + sum-over-dt.
// Grid (8,64), block 256 = 8 warps; warp owns 2 anchors sequentially.
// Per warp: 8KB smem B-fragment buffer (h1 as tf32, fragment-major).
// ---------------------------------------------------------------------------
__global__ void __launch_bounds__(CONV_THREADS, 2) conv_kernel(
    const float* __restrict__ xyzs,
    float* __restrict__ out) {
    extern __shared__ float sm[];
    float* sx = sm;
    float* sy = sm + NPTS;
    float* sz = sm + 2 * NPTS;
    uint32_t* sB = (uint32_t*)(sm + 3 * NPTS);   // 8 warps * 2048 words
    int* sidx = (int*)(sB + 8 * 2048);           // 8 warps * 32

    int tile = blockIdx.x, g = blockIdx.y;
    int b = g >> 4, f = g & 15;
    int tid = threadIdx.x, warp = tid >> 5, lane = tid & 31;
    int gid = lane >> 2, tig = lane & 3;
    uint32_t* wB = sB + warp * 2048;
    int* ib = sidx + warp * KNN;

    int m0 = tile * 16 + warp * 2;
    const float* ap0 = out + ((size_t)g * MANCH + m0) * 3;
    float anc[2][3];
    anc[0][0] = ap0[0]; anc[0][1] = ap0[1]; anc[0][2] = ap0[2];
    anc[1][0] = ap0[3]; anc[1][1] = ap0[4]; anc[1][2] = ap0[5];

    // accM[a][2*mt+hi] = running sum over dt of rowmax for o = mt*16+gid+8*hi
    float accM[2][16];
#pragma unroll
    for (int a = 0; a < 2; a++)
#pragma unroll
        for (int i = 0; i < 16; i++) accM[a][i] = 0.0f;

    for (int dt = -1; dt <= 1; dt++) {
        int t = 2 * f + dt;
        t = t < 0 ? 0 : (t > 31 ? 31 : t);
        const float* frame = xyzs + ((size_t)(b * 32 + t)) * NPTS * 3;
        __syncthreads();
        for (int i = tid; i < NPTS; i += CONV_THREADS) {
            sx[i] = frame[3 * i + 0];
            sy[i] = frame[3 * i + 1];
            sz[i] = frame[3 * i + 2];
        }
        __syncthreads();
        float dtf = (float)dt;

        for (int a = 0; a < 2; a++) {
            float ax = anc[a][0], ay = anc[a][1], az = anc[a][2];

            // ---- ball query (exact fp32; lane = neighbor slot k)
            int count = 0;
            for (int base = 0; base < NPTS && count < KNN; base += 32) {
                int i = base + lane;
                float d2 = dist2_precise(ax, ay, az, sx[i], sy[i], sz[i]);
                bool within = d2 < RR2;
                unsigned msk = __ballot_sync(0xffffffffu, within);
                int pos = count + __popc(msk & ((1u << lane) - 1u));
                if (within && pos < KNN) ib[pos] = i;
                count += __popc(msk);
            }
            __syncwarp();
            int myIdx = 0;
            if (count > 0) myIdx = ib[lane < count ? lane : 0];

            float dx = sx[myIdx] - ax;
            float dy = sy[myIdx] - ay;
            float dz = sz[myIdx] - az;

            // ---- layer 1 (fp32) -> tf32 B fragments in smem
            // B frag (kt,nt): lane l wants b0=h1[nt*8+(l>>2)][kt*8+(l&3)],
            //                 b1 = same row, ch+4.
            // Producer lane k = this lane (k slot): h = lane>>3, w8 = lane&7.
            {
                int h = lane >> 3, w8 = lane & 7;
#pragma unroll
                for (int kt = 0; kt < 8; kt++) {
                    float hv[8];
#pragma unroll
                    for (int c = 0; c < 8; c++) {
                        float4 w = cWd[kt * 8 + c];
                        float v = fmaf(w.x, dx, fmaf(w.y, dy,
                                  fmaf(w.z, dz, w.w * dtf)));
                        hv[c] = fmaxf(v, 0.0f);
                    }
#pragma unroll
                    for (int tg = 0; tg < 4; tg++) {
                        uint2 v;
                        v.x = f2tf32(hv[tg]);
                        v.y = f2tf32(hv[tg + 4]);
                        *(uint2*)(wB + (kt * 4 + h) * 64 + 8 * w8 + 2 * tg) = v;
                    }
                }
            }
            __syncwarp();

            // ---- layer 2: D[128 o x 32 k] via 256 mma.m16n8k8 (tf32)
#pragma unroll 1
            for (int mt = 0; mt < 8; mt++) {
                float d[4][4];
#pragma unroll
                for (int nt = 0; nt < 4; nt++)
#pragma unroll
                    for (int r = 0; r < 4; r++) d[nt][r] = 0.0f;

#pragma unroll
                for (int kt = 0; kt < 8; kt++) {
                    uint4 afr = *(const uint4*)&gWmF[(mt * 8 + kt) * 128 + lane * 4];
#pragma unroll
                    for (int nt = 0; nt < 4; nt++) {
                        uint2 bf = *(const uint2*)(wB + (kt * 4 + nt) * 64 + 2 * lane);
                        mma_tf32(d[nt][0], d[nt][1], d[nt][2], d[nt][3],
                                 afr.x, afr.y, afr.z, afr.w, bf.x, bf.y);
                    }
                }
                // epilogue: max over k (cols), relu, accumulate over dt
                float mlo = fmaxf(d[0][0], d[0][1]);
                float mhi = fmaxf(d[0][2], d[0][3]);
#pragma unroll
                for (int nt = 1; nt < 4; nt++) {
                    mlo = fmaxf(mlo, fmaxf(d[nt][0], d[nt][1]));
                    mhi = fmaxf(mhi, fmaxf(d[nt][2], d[nt][3]));
                }
                mlo = fmaxf(mlo, __shfl_xor_sync(0xffffffffu, mlo, 1));
                mlo = fmaxf(mlo, __shfl_xor_sync(0xffffffffu, mlo, 2));
                mhi = fmaxf(mhi, __shfl_xor_sync(0xffffffffu, mhi, 1));
                mhi = fmaxf(mhi, __shfl_xor_sync(0xffffffffu, mhi, 2));
                accM[a][2 * mt]     += fmaxf(mlo, 0.0f);
                accM[a][2 * mt + 1] += fmaxf(mhi, 0.0f);
            }
            __syncwarp();  // B buffer reads done before next anchor overwrites
        }
    }

    // ---- write new_features: out[b,f,o,m]; lanes with tig==0 own the values
    float* feat = out + (size_t)GTOT * MANCH * 3;
    if (tig == 0) {
#pragma unroll
        for (int a = 0; a < 2; a++) {
            int m = m0 + a;
#pragma unroll
            for (int mt = 0; mt < 8; mt++) {
                int o_lo = mt * 16 + gid;
                feat[((size_t)g * GC1 + o_lo) * MANCH + m]       = accM[a][2 * mt];
                feat[((size_t)g * GC1 + o_lo + 8) * MANCH + m]   = accM[a][2 * mt + 1];
            }
        }
    }
}

extern "C" void kernel_launch(void* const* d_in, const int* in_sizes, int n_in,
                              void* d_out, int out_size) {
    const float* xyzs = (const float*)d_in[0];
    const float* Wd   = (const float*)d_in[1];
    const float* Wm   = (const float*)d_in[2];
    float* out = (float*)d_out;

    cudaMemcpyToSymbolAsync(cWd, Wd, GC0 * 4 * sizeof(float), 0,
                            cudaMemcpyDeviceToDevice);

    size_t smA = (size_t)3 * NPTS * sizeof(float);
    size_t smB = (size_t)3 * NPTS * sizeof(float)     // points  (48K)
               + (size_t)8 * 2048 * sizeof(uint32_t)  // B frags (64K)
               + (size_t)8 * KNN * sizeof(int);       // ball idx (1K)

    cudaFuncSetAttribute(fps_kernel,  cudaFuncAttributeMaxDynamicSharedMemorySize, (int)smA);
    cudaFuncSetAttribute(conv_kernel, cudaFuncAttributeMaxDynamicSharedMemorySize, (int)smB);

    prep_kernel<<<32, 256>>>(Wm);
    fps_kernel<<<GTOT, FPS_THREADS, smA>>>(xyzs, out);
    conv_kernel<<<dim3(8, GTOT), CONV_THREADS, smB>>>(xyzs, out);
}